// round 4
// baseline (speedup 1.0000x reference)
#include <cuda_runtime.h>

// Problem dims (fixed by setup_inputs): B=1, C=32, H=128, W=256, D=48
// out: [1, 2C=64, D=48, H=128, W=256] f32
#define HH 128
#define WW 256
#define CC 32
#define DD 48

constexpr int HW    = HH * WW;        // 32768
constexpr long DHW  = (long)DD * HW;  // 1572864

__global__ __launch_bounds__(256, 3)
void cost_volume_kernel(const float* __restrict__ x,
                        const float* __restrict__ y,
                        const float* __restrict__ disp,
                        float* __restrict__ out)
{
    // Row-interleaved y cache: smY[c*256 + x] = {y[c][y0][x], y[c][y0+1][x]}
    // One aligned LDS.64 fetches BOTH vertical corners. 64 KB total.
    extern __shared__ float2 smY[];

    const int h      = blockIdx.y;   // 0..127
    const int dchunk = blockIdx.x;   // 0..11  (4 d per block)
    const int tid    = threadIdx.x;  // 256 threads

    // iy depends only on h
    const float gy1 = (float)h / 63.5f;
    const float iy  = (gy1 * 128.0f - 1.0f) * 0.5f;
    const float y0f = floorf(iy);
    const float wy  = iy - y0f;
    const int   y0  = (int)y0f;
    const bool  vr0 = ((unsigned)y0       < (unsigned)HH);
    const bool  vr1 = ((unsigned)(y0 + 1) < (unsigned)HH);

    // Stage both y rows, interleaved. Consecutive lanes -> consecutive 8B smem
    // words: conflict-free STS.64. Loads are coalesced scalar LDG (L2-hot).
    for (int i = tid; i < CC * WW; i += 256) {
        const int c  = i >> 8;    // 0..31
        const int xx = i & 255;   // 0..255
        const float* yp = y + (c * HH + y0) * WW + xx;
        float v0 = vr0 ? __ldg(yp)      : 0.0f;
        float v1 = vr1 ? __ldg(yp + WW) : 0.0f;
        smY[i] = make_float2(v0, v1);
    }
    __syncthreads();

    // Thread mapping: tid>>6 = local d (0..3), tid&63 -> 4 consecutive w
    const int dloc = tid >> 6;
    const int d    = dchunk * 4 + dloc;
    const int w0   = (tid & 63) << 2;

    const float4 dv = *(const float4*)(disp + (d * HH + h) * WW + w0);
    const float darr[4] = {dv.x, dv.y, dv.z, dv.w};

    int   xa[4], xb[4];
    float w00[4], w01[4], w10[4], w11[4];
    const float omwy = 1.0f - wy;

    #pragma unroll
    for (int j = 0; j < 4; ++j) {
        const float cur = (float)(w0 + j) - darr[j];
        const float t   = cur / 127.5f;
        const float ixv = (t * 256.0f - 1.0f) * 0.5f;
        const float x0f = floorf(ixv);
        const float wx  = ixv - x0f;
        const int   x0i = (int)x0f;
        const int   x1i = x0i + 1;
        const float m0  = ((unsigned)x0i < (unsigned)WW) ? 1.0f : 0.0f;
        const float m1  = ((unsigned)x1i < (unsigned)WW) ? 1.0f : 0.0f;
        xa[j] = min(max(x0i, 0), WW - 1);
        xb[j] = min(max(x1i, 0), WW - 1);
        const float omwx = 1.0f - wx;
        w00[j] = omwx * omwy * m0;   // (y0,x0)
        w01[j] = wx   * omwy * m1;   // (y0,x1)
        w10[j] = omwx * wy   * m0;   // (y1,x0)
        w11[j] = wx   * wy   * m1;   // (y1,x1)
    }

    const float* xrow = x + h * WW + w0;
    float* outL = out + (long)d * HW + (long)h * WW + w0;   // left half (c<32)
    float* outR = outL + (long)CC * DHW;                    // warped half

    #pragma unroll 4
    for (int c = 0; c < CC; ++c) {
        const float2* base = smY + (c << 8);

        float4 o;
        {
            const float2 pa = base[xa[0]], pb = base[xb[0]];
            o.x = pa.x * w00[0] + pb.x * w01[0] + pa.y * w10[0] + pb.y * w11[0];
        }
        {
            const float2 pa = base[xa[1]], pb = base[xb[1]];
            o.y = pa.x * w00[1] + pb.x * w01[1] + pa.y * w10[1] + pb.y * w11[1];
        }
        {
            const float2 pa = base[xa[2]], pb = base[xb[2]];
            o.z = pa.x * w00[2] + pb.x * w01[2] + pa.y * w10[2] + pb.y * w11[2];
        }
        {
            const float2 pa = base[xa[3]], pb = base[xb[3]];
            o.w = pa.x * w00[3] + pb.x * w01[3] + pa.y * w10[3] + pb.y * w11[3];
        }
        *(float4*)(outR + (long)c * DHW) = o;

        // Left half: broadcast x over d (x row L1-hot across the block's 4 d's)
        const float4 xv = __ldg((const float4*)(xrow + c * HW));
        *(float4*)(outL + (long)c * DHW) = xv;
    }
}

extern "C" void kernel_launch(void* const* d_in, const int* in_sizes, int n_in,
                              void* d_out, int out_size)
{
    const float* x    = (const float*)d_in[0];
    const float* y    = (const float*)d_in[1];
    const float* disp = (const float*)d_in[2];
    float* out = (float*)d_out;

    const int smem_bytes = CC * WW * (int)sizeof(float2);  // 64 KB
    cudaFuncSetAttribute(cost_volume_kernel,
                         cudaFuncAttributeMaxDynamicSharedMemorySize, smem_bytes);

    dim3 grid(DD / 4, HH);   // (12, 128) = 1536 blocks
    cost_volume_kernel<<<grid, 256, smem_bytes>>>(x, y, disp, out);
}